// round 4
// baseline (speedup 1.0000x reference)
#include <cuda_runtime.h>
#include <cuda_fp16.h>
#include <cuda_bf16.h>
#include <cstdint>

// ---------------------------------------------------------------------------
// QuantLinear: nvfp4 fake-quant(x), fake-quant(W), then x_q @ W_q^T + b
// x: [4,2048,4096] f32  -> M=8192, K=4096
// W: [4096,4096]   f32  -> N=4096, K=4096
// b: [4096]        f32
// out: [8192,4096] f32
// ---------------------------------------------------------------------------

#define MAX_M 8192
#define KDIM  4096
#define NDIM  4096

// Scratch (static device globals: allocation-free, graph-capturable)
__device__ unsigned int g_amax[2];
__device__ __half g_xq[(size_t)MAX_M * KDIM];   // 64 MB
__device__ __half g_wq[(size_t)NDIM * KDIM];    // 32 MB

// ---------------------------------------------------------------------------
// round-to-tiny-float, matching the reference's math exactly:
//   e = max(floor(log2|x|), min_exp); step = 2^(e-mant);
//   q = min(rint(|x|/step)*step, maxv); result = sign(x)*q
// frexpf/ldexpf are exact; rintf is round-half-even (== jnp.round);
// __fdiv_rn/__fmul_rn force IEEE regardless of fast-math flags.
// ---------------------------------------------------------------------------
__device__ __forceinline__ float roundfp(float x, int mant, int min_exp, float maxv) {
    float a = fabsf(x);
    int e;
    frexpf(a, &e);          // a = m * 2^e, m in [0.5,1)  -> floor(log2 a) = e-1
    e -= 1;
    if (e < min_exp) e = min_exp;
    float step = ldexpf(1.0f, e - mant);
    float q = fminf(__fmul_rn(rintf(__fdiv_rn(a, step)), step), maxv);
    return (x < 0.0f) ? -q : q;
}

__global__ void init_kernel() {
    g_amax[0] = 0u;
    g_amax[1] = 0u;
}

__global__ void amax_kernel(const float* __restrict__ x, int n4, int slot) {
    float m = 0.0f;
    for (int i = blockIdx.x * blockDim.x + threadIdx.x; i < n4;
         i += gridDim.x * blockDim.x) {
        float4 v = reinterpret_cast<const float4*>(x)[i];
        m = fmaxf(m, fmaxf(fmaxf(fabsf(v.x), fabsf(v.y)),
                           fmaxf(fabsf(v.z), fabsf(v.w))));
    }
    #pragma unroll
    for (int o = 16; o; o >>= 1)
        m = fmaxf(m, __shfl_xor_sync(0xffffffffu, m, o));
    if ((threadIdx.x & 31) == 0)
        atomicMax(&g_amax[slot], __float_as_uint(m));  // order-independent
}

// One thread = one 16-element nvfp4 micro-block (contiguous along last axis).
__global__ void quant_kernel(const float* __restrict__ in,
                             __half* __restrict__ out,
                             int nblk, int slot) {
    int b = blockIdx.x * blockDim.x + threadIdx.x;
    if (b >= nblk) return;
    float amax   = __uint_as_float(g_amax[slot]);
    float gscale = __fdiv_rn(2688.0f, amax);   // 448 * 6 / amax

    const float4* p = reinterpret_cast<const float4*>(in + (size_t)b * 16);
    float4 v0 = p[0], v1 = p[1], v2 = p[2], v3 = p[3];
    float vals[16] = {v0.x, v0.y, v0.z, v0.w, v1.x, v1.y, v1.z, v1.w,
                      v2.x, v2.y, v2.z, v2.w, v3.x, v3.y, v3.z, v3.w};

    float bmax = 0.0f;
    #pragma unroll
    for (int i = 0; i < 16; i++) bmax = fmaxf(bmax, fabsf(vals[i]));

    // block scale: fp8-e4m3 grid (3 mantissa bits, min exp -6, max 448)
    float sv  = __fmul_rn(__fdiv_rn(bmax, 6.0f), gscale);
    float scq = roundfp(sv, 3, -6, 448.0f);
    float sc  = __fdiv_rn(scq, gscale);
    float scs = (sc > 0.0f) ? sc : 1.0f;

    __half h[16];
    #pragma unroll
    for (int i = 0; i < 16; i++) {
        // fp4-e2m1 grid: 1 mantissa bit, min exp 0, max 6
        float q = roundfp(__fdiv_rn(vals[i], scs), 1, 0, 6.0f);
        h[i] = __float2half_rn(__fmul_rn(q, sc));
    }
    // 16 halves = 32 bytes, 32B-aligned (b*32)
    uint4* o = reinterpret_cast<uint4*>(out + (size_t)b * 16);
    o[0] = reinterpret_cast<uint4*>(h)[0];
    o[1] = reinterpret_cast<uint4*>(h)[1];
}

// ---------------------------------------------------------------------------
// f16 HMMA GEMM: C[M,N] = A[M,K] * B[N,K]^T + bias
// CTA tile 128x128, K-tile 32, 8 warps (4x2), warp tile 32x64,
// mma.sync.m16n8k16.row.col.f32.f16.f16.f32
// ---------------------------------------------------------------------------
__device__ __forceinline__ void mma_16816(float* d, const uint32_t* a,
                                          const uint32_t* b) {
    asm volatile(
        "mma.sync.aligned.m16n8k16.row.col.f32.f16.f16.f32 "
        "{%0,%1,%2,%3}, {%4,%5,%6,%7}, {%8,%9}, {%0,%1,%2,%3};\n"
        : "+f"(d[0]), "+f"(d[1]), "+f"(d[2]), "+f"(d[3])
        : "r"(a[0]), "r"(a[1]), "r"(a[2]), "r"(a[3]), "r"(b[0]), "r"(b[1]));
}

__global__ void __launch_bounds__(256) gemm_kernel(
    const __half* __restrict__ A,   // [M,K]
    const __half* __restrict__ B,   // [N,K]
    const float* __restrict__ bias, // [N]
    float* __restrict__ C,          // [M,N]
    int M, int N, int K) {
    __shared__ __half As[128][40];  // pad 8 -> conflict-free frag loads
    __shared__ __half Bs[128][40];

    const int t    = threadIdx.x;
    const int m0   = blockIdx.y * 128;
    const int n0   = blockIdx.x * 128;
    const int warp = t >> 5;
    const int lane = t & 31;
    const int wm   = (warp >> 1) * 32;   // warp row offset (4 warps in M)
    const int wn   = (warp & 1) * 64;    // warp col offset (2 warps in N)
    const int ar   = lane >> 2;          // fragment row-in-8
    const int ac   = (lane & 3) * 2;     // fragment col pair

    float acc[2][8][4];
    #pragma unroll
    for (int i = 0; i < 2; i++)
        #pragma unroll
        for (int j = 0; j < 8; j++)
            #pragma unroll
            for (int r = 0; r < 4; r++) acc[i][j][r] = 0.0f;

    for (int k0 = 0; k0 < K; k0 += 32) {
        // load A and B tiles: 128x32 halves each, uint2 (4-half) chunks
        #pragma unroll
        for (int i = 0; i < 4; i++) {
            int c   = t + i * 256;          // 0..1023
            int row = c >> 3;               // 8 chunks per 32-wide row
            int col = (c & 7) * 4;
            *(uint2*)&As[row][col] =
                *(const uint2*)&A[(size_t)(m0 + row) * K + k0 + col];
            *(uint2*)&Bs[row][col] =
                *(const uint2*)&B[(size_t)(n0 + row) * K + k0 + col];
        }
        __syncthreads();

        #pragma unroll
        for (int kk = 0; kk < 32; kk += 16) {
            uint32_t afr[2][4], bfr[8][2];
            #pragma unroll
            for (int i = 0; i < 2; i++) {
                int r = wm + i * 16 + ar;
                afr[i][0] = *(uint32_t*)&As[r][kk + ac];
                afr[i][1] = *(uint32_t*)&As[r + 8][kk + ac];
                afr[i][2] = *(uint32_t*)&As[r][kk + ac + 8];
                afr[i][3] = *(uint32_t*)&As[r + 8][kk + ac + 8];
            }
            #pragma unroll
            for (int j = 0; j < 8; j++) {
                int n = wn + j * 8 + ar;
                bfr[j][0] = *(uint32_t*)&Bs[n][kk + ac];
                bfr[j][1] = *(uint32_t*)&Bs[n][kk + ac + 8];
            }
            #pragma unroll
            for (int i = 0; i < 2; i++)
                #pragma unroll
                for (int j = 0; j < 8; j++)
                    mma_16816(acc[i][j], afr[i], bfr[j]);
        }
        __syncthreads();
    }

    // epilogue: + bias, fp32 out
    #pragma unroll
    for (int i = 0; i < 2; i++) {
        #pragma unroll
        for (int j = 0; j < 8; j++) {
            int r = m0 + wm + i * 16 + ar;
            int n = n0 + wn + j * 8 + ac;
            float bv0 = bias[n], bv1 = bias[n + 1];
            float2 o0 = {acc[i][j][0] + bv0, acc[i][j][1] + bv1};
            float2 o1 = {acc[i][j][2] + bv0, acc[i][j][3] + bv1};
            *(float2*)&C[(size_t)r * N + n]       = o0;
            *(float2*)&C[(size_t)(r + 8) * N + n] = o1;
        }
    }
}

// ---------------------------------------------------------------------------
extern "C" void kernel_launch(void* const* d_in, const int* in_sizes, int n_in,
                              void* d_out, int out_size) {
    const float* x = (const float*)d_in[0];
    const float* W = (const float*)d_in[1];
    const float* b = (const float*)d_in[2];
    float* out = (float*)d_out;

    const int K = KDIM;
    const int N = NDIM;
    const int M = in_sizes[0] / K;          // 8192

    __half* xq;  cudaGetSymbolAddress((void**)&xq, g_xq);
    __half* wq;  cudaGetSymbolAddress((void**)&wq, g_wq);

    init_kernel<<<1, 1>>>();

    amax_kernel<<<1024, 256>>>(x, (M * K) / 4, 0);
    amax_kernel<<<1024, 256>>>(W, (N * K) / 4, 1);

    int nblk_x = (M * K) / 16;
    int nblk_w = (N * K) / 16;
    quant_kernel<<<(nblk_x + 255) / 256, 256>>>(x, xq, nblk_x, 0);
    quant_kernel<<<(nblk_w + 255) / 256, 256>>>(W, wq, nblk_w, 1);

    dim3 grid(N / 128, M / 128);
    gemm_kernel<<<grid, 256>>>(xq, wq, b, out, M, N, K);
}

// round 5
// speedup vs baseline: 1.0064x; 1.0064x over previous
#include <cuda_runtime.h>
#include <cuda_fp16.h>
#include <cuda_bf16.h>
#include <cstdint>

// ---------------------------------------------------------------------------
// QuantLinear: nvfp4 fake-quant(x), fake-quant(W), then x_q @ W_q^T + b
// x: [4,2048,4096] f32  -> M=8192, K=4096
// W: [4096,4096]   f32  -> N=4096, K=4096
// b: [4096]        f32
// out: [8192,4096] f32
// ---------------------------------------------------------------------------

#define MAX_M 8192
#define KDIM  4096
#define NDIM  4096

// Scratch (static device globals: allocation-free, graph-capturable)
__device__ unsigned int g_amax[2];
__device__ __half g_xq[(size_t)MAX_M * KDIM];   // 64 MB
__device__ __half g_wq[(size_t)NDIM * KDIM];    // 32 MB

// ---------------------------------------------------------------------------
// round-to-tiny-float, matching the reference's math exactly:
//   e = max(floor(log2|x|), min_exp); step = 2^(e-mant);
//   q = min(rint(|x|/step)*step, maxv); result = sign(x)*q
// frexpf/ldexpf are exact; rintf is round-half-even (== jnp.round);
// __fdiv_rn/__fmul_rn force IEEE regardless of fast-math flags.
// ---------------------------------------------------------------------------
__device__ __forceinline__ float roundfp(float x, int mant, int min_exp, float maxv) {
    float a = fabsf(x);
    int e;
    frexpf(a, &e);          // a = m * 2^e, m in [0.5,1)  -> floor(log2 a) = e-1
    e -= 1;
    if (e < min_exp) e = min_exp;
    float step = ldexpf(1.0f, e - mant);
    float q = fminf(__fmul_rn(rintf(__fdiv_rn(a, step)), step), maxv);
    return (x < 0.0f) ? -q : q;
}

__global__ void init_kernel() {
    g_amax[0] = 0u;
    g_amax[1] = 0u;
}

__global__ void amax_kernel(const float* __restrict__ x, int n4, int slot) {
    float m = 0.0f;
    for (int i = blockIdx.x * blockDim.x + threadIdx.x; i < n4;
         i += gridDim.x * blockDim.x) {
        float4 v = reinterpret_cast<const float4*>(x)[i];
        m = fmaxf(m, fmaxf(fmaxf(fabsf(v.x), fabsf(v.y)),
                           fmaxf(fabsf(v.z), fabsf(v.w))));
    }
    #pragma unroll
    for (int o = 16; o; o >>= 1)
        m = fmaxf(m, __shfl_xor_sync(0xffffffffu, m, o));
    if ((threadIdx.x & 31) == 0)
        atomicMax(&g_amax[slot], __float_as_uint(m));  // order-independent
}

// One thread = one 16-element nvfp4 micro-block (contiguous along last axis).
__global__ void quant_kernel(const float* __restrict__ in,
                             __half* __restrict__ out,
                             int nblk, int slot) {
    int b = blockIdx.x * blockDim.x + threadIdx.x;
    if (b >= nblk) return;
    float amax   = __uint_as_float(g_amax[slot]);
    float gscale = __fdiv_rn(2688.0f, amax);   // 448 * 6 / amax

    const float4* p = reinterpret_cast<const float4*>(in + (size_t)b * 16);
    float4 v0 = p[0], v1 = p[1], v2 = p[2], v3 = p[3];
    float vals[16] = {v0.x, v0.y, v0.z, v0.w, v1.x, v1.y, v1.z, v1.w,
                      v2.x, v2.y, v2.z, v2.w, v3.x, v3.y, v3.z, v3.w};

    float bmax = 0.0f;
    #pragma unroll
    for (int i = 0; i < 16; i++) bmax = fmaxf(bmax, fabsf(vals[i]));

    // block scale: fp8-e4m3 grid (3 mantissa bits, min exp -6, max 448)
    float sv  = __fmul_rn(__fdiv_rn(bmax, 6.0f), gscale);
    float scq = roundfp(sv, 3, -6, 448.0f);
    float sc  = __fdiv_rn(scq, gscale);
    float scs = (sc > 0.0f) ? sc : 1.0f;

    __half h[16];
    #pragma unroll
    for (int i = 0; i < 16; i++) {
        // fp4-e2m1 grid: 1 mantissa bit, min exp 0, max 6
        float q = roundfp(__fdiv_rn(vals[i], scs), 1, 0, 6.0f);
        h[i] = __float2half_rn(__fmul_rn(q, sc));
    }
    // 16 halves = 32 bytes, 32B-aligned (b*32)
    uint4* o = reinterpret_cast<uint4*>(out + (size_t)b * 16);
    o[0] = reinterpret_cast<uint4*>(h)[0];
    o[1] = reinterpret_cast<uint4*>(h)[1];
}

// ---------------------------------------------------------------------------
// f16 HMMA GEMM: C[M,N] = A[M,K] * B[N,K]^T + bias
// CTA tile 128x128, K-tile 32, 8 warps (4x2), warp tile 32x64,
// mma.sync.m16n8k16.row.col.f32.f16.f16.f32
// ---------------------------------------------------------------------------
__device__ __forceinline__ void mma_16816(float* d, const uint32_t* a,
                                          const uint32_t* b) {
    asm volatile(
        "mma.sync.aligned.m16n8k16.row.col.f32.f16.f16.f32 "
        "{%0,%1,%2,%3}, {%4,%5,%6,%7}, {%8,%9}, {%0,%1,%2,%3};\n"
        : "+f"(d[0]), "+f"(d[1]), "+f"(d[2]), "+f"(d[3])
        : "r"(a[0]), "r"(a[1]), "r"(a[2]), "r"(a[3]), "r"(b[0]), "r"(b[1]));
}

__global__ void __launch_bounds__(256) gemm_kernel(
    const __half* __restrict__ A,   // [M,K]
    const __half* __restrict__ B,   // [N,K]
    const float* __restrict__ bias, // [N]
    float* __restrict__ C,          // [M,N]
    int M, int N, int K) {
    __shared__ __half As[128][40];  // pad 8 -> conflict-free frag loads
    __shared__ __half Bs[128][40];

    const int t    = threadIdx.x;
    const int m0   = blockIdx.y * 128;
    const int n0   = blockIdx.x * 128;
    const int warp = t >> 5;
    const int lane = t & 31;
    const int wm   = (warp >> 1) * 32;   // warp row offset (4 warps in M)
    const int wn   = (warp & 1) * 64;    // warp col offset (2 warps in N)
    const int ar   = lane >> 2;          // fragment row-in-8
    const int ac   = (lane & 3) * 2;     // fragment col pair

    float acc[2][8][4];
    #pragma unroll
    for (int i = 0; i < 2; i++)
        #pragma unroll
        for (int j = 0; j < 8; j++)
            #pragma unroll
            for (int r = 0; r < 4; r++) acc[i][j][r] = 0.0f;

    for (int k0 = 0; k0 < K; k0 += 32) {
        // load A and B tiles: 128x32 halves each, uint2 (4-half) chunks
        #pragma unroll
        for (int i = 0; i < 4; i++) {
            int c   = t + i * 256;          // 0..1023
            int row = c >> 3;               // 8 chunks per 32-wide row
            int col = (c & 7) * 4;
            *(uint2*)&As[row][col] =
                *(const uint2*)&A[(size_t)(m0 + row) * K + k0 + col];
            *(uint2*)&Bs[row][col] =
                *(const uint2*)&B[(size_t)(n0 + row) * K + k0 + col];
        }
        __syncthreads();

        #pragma unroll
        for (int kk = 0; kk < 32; kk += 16) {
            uint32_t afr[2][4], bfr[8][2];
            #pragma unroll
            for (int i = 0; i < 2; i++) {
                int r = wm + i * 16 + ar;
                afr[i][0] = *(uint32_t*)&As[r][kk + ac];
                afr[i][1] = *(uint32_t*)&As[r + 8][kk + ac];
                afr[i][2] = *(uint32_t*)&As[r][kk + ac + 8];
                afr[i][3] = *(uint32_t*)&As[r + 8][kk + ac + 8];
            }
            #pragma unroll
            for (int j = 0; j < 8; j++) {
                int n = wn + j * 8 + ar;
                bfr[j][0] = *(uint32_t*)&Bs[n][kk + ac];
                bfr[j][1] = *(uint32_t*)&Bs[n][kk + ac + 8];
            }
            #pragma unroll
            for (int i = 0; i < 2; i++)
                #pragma unroll
                for (int j = 0; j < 8; j++)
                    mma_16816(acc[i][j], afr[i], bfr[j]);
        }
        __syncthreads();
    }

    // epilogue: + bias, fp32 out
    #pragma unroll
    for (int i = 0; i < 2; i++) {
        #pragma unroll
        for (int j = 0; j < 8; j++) {
            int r = m0 + wm + i * 16 + ar;
            int n = n0 + wn + j * 8 + ac;
            float bv0 = bias[n], bv1 = bias[n + 1];
            float2 o0 = {acc[i][j][0] + bv0, acc[i][j][1] + bv1};
            float2 o1 = {acc[i][j][2] + bv0, acc[i][j][3] + bv1};
            *(float2*)&C[(size_t)r * N + n]       = o0;
            *(float2*)&C[(size_t)(r + 8) * N + n] = o1;
        }
    }
}

// ---------------------------------------------------------------------------
extern "C" void kernel_launch(void* const* d_in, const int* in_sizes, int n_in,
                              void* d_out, int out_size) {
    const float* x = (const float*)d_in[0];
    const float* W = (const float*)d_in[1];
    const float* b = (const float*)d_in[2];
    float* out = (float*)d_out;

    const int K = KDIM;
    const int N = NDIM;
    const int M = in_sizes[0] / K;          // 8192

    __half* xq;  cudaGetSymbolAddress((void**)&xq, g_xq);
    __half* wq;  cudaGetSymbolAddress((void**)&wq, g_wq);

    init_kernel<<<1, 1>>>();

    amax_kernel<<<1024, 256>>>(x, (M * K) / 4, 0);
    amax_kernel<<<1024, 256>>>(W, (N * K) / 4, 1);

    int nblk_x = (M * K) / 16;
    int nblk_w = (N * K) / 16;
    quant_kernel<<<(nblk_x + 255) / 256, 256>>>(x, xq, nblk_x, 0);
    quant_kernel<<<(nblk_w + 255) / 256, 256>>>(W, wq, nblk_w, 1);

    dim3 grid(N / 128, M / 128);
    gemm_kernel<<<grid, 256>>>(xq, wq, b, out, M, N, K);
}

// round 7
// speedup vs baseline: 1.1919x; 1.1842x over previous
#include <cuda_runtime.h>
#include <cuda_fp16.h>
#include <cuda_bf16.h>
#include <cstdint>

// ---------------------------------------------------------------------------
// QuantLinear: nvfp4 fake-quant(x), fake-quant(W), then x_q @ W_q^T + b
// x: [4,2048,4096] f32 -> M=8192,K=4096 ; W: [4096,4096] ; b:[4096] ; out f32
// R6: harness PTX target is sm_103 (no 'a') -> tcgen05 unavailable.
//     HMMA mma.sync GEMM with cp.async 4-stage pipeline, CTA tile 256x128.
// ---------------------------------------------------------------------------

#define MAX_M 8192
#define KDIM  4096
#define NDIM  4096

__device__ unsigned int g_amax[2];
__device__ __half g_xq[(size_t)MAX_M * KDIM];   // 64 MB
__device__ __half g_wq[(size_t)NDIM * KDIM];    // 32 MB

// ---------------------------------------------------------------------------
// round-to-tiny-float, bit-exact vs reference:
//   e = max(floor(log2|x|), min_exp); step = 2^(e-mant);
//   q = min(rint(|x|/step)*step, maxv); result = sign(x)*q
// floor(log2) read from the exponent field (exact for normals; zero/subnormal
// clamp to min_exp exactly like the reference). Multiplying by a constructed
// power of two is exact, so this matches the frexpf/ldexpf/IEEE-div chain.
// ---------------------------------------------------------------------------
__device__ __forceinline__ float roundfp(float x, int mant, int min_exp, float maxv) {
    float a = fabsf(x);
    int e = (int)(__float_as_uint(a) >> 23) - 127;   // floor(log2 a) for normals
    if (e < min_exp) e = min_exp;
    float step  = __uint_as_float((unsigned)(e - mant + 127) << 23);
    float istep = __uint_as_float((unsigned)(127 - (e - mant)) << 23);
    float q = fminf(__fmul_rn(rintf(__fmul_rn(a, istep)), step), maxv);
    return (x < 0.0f) ? -q : q;
}

__global__ void init_kernel() { g_amax[0] = 0u; g_amax[1] = 0u; }

__global__ void amax_kernel(const float* __restrict__ x, int n4, int slot) {
    float m = 0.0f;
    for (int i = blockIdx.x * blockDim.x + threadIdx.x; i < n4;
         i += gridDim.x * blockDim.x) {
        float4 v = reinterpret_cast<const float4*>(x)[i];
        m = fmaxf(m, fmaxf(fmaxf(fabsf(v.x), fabsf(v.y)),
                           fmaxf(fabsf(v.z), fabsf(v.w))));
    }
    #pragma unroll
    for (int o = 16; o; o >>= 1)
        m = fmaxf(m, __shfl_xor_sync(0xffffffffu, m, o));
    if ((threadIdx.x & 31) == 0)
        atomicMax(&g_amax[slot], __float_as_uint(m));
}

// One thread = one 16-element nvfp4 micro-block.
__global__ void quant_kernel(const float* __restrict__ in,
                             __half* __restrict__ out,
                             int nblk, int slot) {
    int b = blockIdx.x * blockDim.x + threadIdx.x;
    if (b >= nblk) return;
    float amax   = __uint_as_float(g_amax[slot]);
    float gscale = __fdiv_rn(2688.0f, amax);   // 448 * 6 / amax

    const float4* p = reinterpret_cast<const float4*>(in + (size_t)b * 16);
    float4 v0 = p[0], v1 = p[1], v2 = p[2], v3 = p[3];
    float vals[16] = {v0.x, v0.y, v0.z, v0.w, v1.x, v1.y, v1.z, v1.w,
                      v2.x, v2.y, v2.z, v2.w, v3.x, v3.y, v3.z, v3.w};

    float bmax = 0.0f;
    #pragma unroll
    for (int i = 0; i < 16; i++) bmax = fmaxf(bmax, fabsf(vals[i]));

    float sv  = __fmul_rn(__fdiv_rn(bmax, 6.0f), gscale);
    float scq = roundfp(sv, 3, -6, 448.0f);
    float sc  = __fdiv_rn(scq, gscale);
    float scs = (sc > 0.0f) ? sc : 1.0f;

    __half h[16];
    #pragma unroll
    for (int i = 0; i < 16; i++) {
        float q = roundfp(__fdiv_rn(vals[i], scs), 1, 0, 6.0f);
        h[i] = __float2half_rn(__fmul_rn(q, sc));
    }
    uint4* o = reinterpret_cast<uint4*>(out + (size_t)b * 16);
    o[0] = reinterpret_cast<uint4*>(h)[0];
    o[1] = reinterpret_cast<uint4*>(h)[1];
}

// ---------------------------------------------------------------------------
// HMMA GEMM with cp.async multistage pipeline.
// C[M,N] = A[M,K] * B[N,K]^T + bias
// CTA tile 256(M) x 128(N), K-tile 32, 512 threads = 16 warps (4x4),
// warp tile 64x32, mma.sync.m16n8k16.f32.f16.f16.f32, 4 stages.
// ---------------------------------------------------------------------------
#define BM 256
#define BN 128
#define BK 32
#define STAGES 4
#define BKP 40                                   // padded row (halves)
#define A_STG (BM * BKP)                         // halves
#define B_STG (BN * BKP)
#define STG_HALVES (A_STG + B_STG)               // 15360 halves = 30720 B
#define GEMM_SMEM (STAGES * STG_HALVES * 2 + 512)

__device__ __forceinline__ uint32_t smem_u32(const void* p) {
    uint32_t a;
    asm("{ .reg .u64 t; cvta.to.shared.u64 t, %1; cvt.u32.u64 %0, t; }"
        : "=r"(a) : "l"(p));
    return a;
}
__device__ __forceinline__ void cpa16(uint32_t s, const void* g) {
    asm volatile("cp.async.cg.shared.global [%0], [%1], 16;"
                 :: "r"(s), "l"(g) : "memory");
}
__device__ __forceinline__ void cpa_commit() {
    asm volatile("cp.async.commit_group;" ::: "memory");
}
template <int N_>
__device__ __forceinline__ void cpa_wait() {
    asm volatile("cp.async.wait_group %0;" :: "n"(N_) : "memory");
}
__device__ __forceinline__ void mma_16816(float* d, const uint32_t* a,
                                          const uint32_t* b) {
    asm volatile(
        "mma.sync.aligned.m16n8k16.row.col.f32.f16.f16.f32 "
        "{%0,%1,%2,%3}, {%4,%5,%6,%7}, {%8,%9}, {%0,%1,%2,%3};\n"
        : "+f"(d[0]), "+f"(d[1]), "+f"(d[2]), "+f"(d[3])
        : "r"(a[0]), "r"(a[1]), "r"(a[2]), "r"(a[3]), "r"(b[0]), "r"(b[1]));
}

__global__ void __launch_bounds__(512, 1) gemm_kernel(
    const __half* __restrict__ A,   // [M,K]
    const __half* __restrict__ B,   // [N,K]
    const float* __restrict__ bias, // [N]
    float* __restrict__ C,          // [M,N]
    int M, int N, int K) {
    extern __shared__ char smem_raw[];
    __half* stg   = (__half*)smem_raw;                       // STAGES tiles
    float*  biass = (float*)(smem_raw + STAGES * STG_HALVES * 2);

    const int t    = threadIdx.x;
    const int m0   = blockIdx.y * BM;
    const int n0   = blockIdx.x * BN;
    const int warp = t >> 5;
    const int lane = t & 31;
    const int wm   = (warp >> 2) * 64;   // 4 warp-rows
    const int wn   = (warp & 3) * 32;    // 4 warp-cols
    const int ar   = lane >> 2;
    const int ac   = (lane & 3) * 2;

    if (t < BN) biass[t] = bias[n0 + t];

    const uint32_t stg_s = smem_u32(stg);
    const int nK = K / BK;               // 128

    // per-thread load slots: A = 1024 16B chunks (2/thread), B = 512 (1/thread)
    const int a_r0 = (t + 0)   >> 2, a_c0 = ((t + 0)   & 3) * 8;
    const int a_r1 = (t + 512) >> 2, a_c1 = ((t + 512) & 3) * 8;
    const int b_r  = t >> 2,         b_c  = (t & 3) * 8;

    auto load_stage = [&](int kt, int s) {
        const uint32_t ab = stg_s + (uint32_t)s * (STG_HALVES * 2);
        const uint32_t bb = ab + A_STG * 2;
        const __half* Ag = A + (size_t)m0 * K + (size_t)kt * BK;
        const __half* Bg = B + (size_t)n0 * K + (size_t)kt * BK;
        cpa16(ab + (a_r0 * BKP + a_c0) * 2, Ag + (size_t)a_r0 * K + a_c0);
        cpa16(ab + (a_r1 * BKP + a_c1) * 2, Ag + (size_t)a_r1 * K + a_c1);
        cpa16(bb + (b_r  * BKP + b_c ) * 2, Bg + (size_t)b_r  * K + b_c);
        cpa_commit();
    };

    // prologue: stages 0..STAGES-2
    #pragma unroll
    for (int s = 0; s < STAGES - 1; s++) load_stage(s, s);

    float acc[4][4][4];
    #pragma unroll
    for (int i = 0; i < 4; i++)
        #pragma unroll
        for (int j = 0; j < 4; j++)
            #pragma unroll
            for (int r = 0; r < 4; r++) acc[i][j][r] = 0.0f;

    for (int k = 0; k < nK; k++) {
        cpa_wait<STAGES - 2>();
        __syncthreads();

        // issue next loads into the stage freed by iteration k-1
        int kl = k + STAGES - 1;
        if (kl > nK - 1) kl = nK - 1;    // uniform redundant tail loads
        load_stage(kl, kl & (STAGES - 1));

        const __half (*As)[BKP] =
            (const __half(*)[BKP])(stg + (k & (STAGES - 1)) * STG_HALVES);
        const __half (*Bs)[BKP] =
            (const __half(*)[BKP])(stg + (k & (STAGES - 1)) * STG_HALVES + A_STG);

        #pragma unroll
        for (int kk = 0; kk < BK; kk += 16) {
            uint32_t afr[4][4], bfr[4][2];
            #pragma unroll
            for (int i = 0; i < 4; i++) {
                int r = wm + i * 16 + ar;
                afr[i][0] = *(const uint32_t*)&As[r][kk + ac];
                afr[i][1] = *(const uint32_t*)&As[r + 8][kk + ac];
                afr[i][2] = *(const uint32_t*)&As[r][kk + ac + 8];
                afr[i][3] = *(const uint32_t*)&As[r + 8][kk + ac + 8];
            }
            #pragma unroll
            for (int j = 0; j < 4; j++) {
                int n = wn + j * 8 + ar;
                bfr[j][0] = *(const uint32_t*)&Bs[n][kk + ac];
                bfr[j][1] = *(const uint32_t*)&Bs[n][kk + ac + 8];
            }
            #pragma unroll
            for (int i = 0; i < 4; i++)
                #pragma unroll
                for (int j = 0; j < 4; j++)
                    mma_16816(acc[i][j], afr[i], bfr[j]);
        }
        __syncthreads();
    }

    // epilogue: + bias, fp32 out
    #pragma unroll
    for (int i = 0; i < 4; i++) {
        #pragma unroll
        for (int j = 0; j < 4; j++) {
            int r = m0 + wm + i * 16 + ar;
            int nn = wn + j * 8 + ac;
            float bv0 = biass[nn], bv1 = biass[nn + 1];
            float2 o0 = {acc[i][j][0] + bv0, acc[i][j][1] + bv1};
            float2 o1 = {acc[i][j][2] + bv0, acc[i][j][3] + bv1};
            *(float2*)&C[(size_t)r * N + n0 + nn]       = o0;
            *(float2*)&C[(size_t)(r + 8) * N + n0 + nn] = o1;
        }
    }
}

// ---------------------------------------------------------------------------
extern "C" void kernel_launch(void* const* d_in, const int* in_sizes, int n_in,
                              void* d_out, int out_size) {
    const float* x = (const float*)d_in[0];
    const float* W = (const float*)d_in[1];
    const float* b = (const float*)d_in[2];
    float* out = (float*)d_out;

    const int K = KDIM;
    const int N = NDIM;
    const int M = in_sizes[0] / K;          // 8192

    __half* xq;  cudaGetSymbolAddress((void**)&xq, g_xq);
    __half* wq;  cudaGetSymbolAddress((void**)&wq, g_wq);

    init_kernel<<<1, 1>>>();
    amax_kernel<<<1024, 256>>>(x, (M * K) / 4, 0);
    amax_kernel<<<1024, 256>>>(W, (N * K) / 4, 1);

    int nblk_x = (M * K) / 16;
    int nblk_w = (N * K) / 16;
    quant_kernel<<<(nblk_x + 255) / 256, 256>>>(x, xq, nblk_x, 0);
    quant_kernel<<<(nblk_w + 255) / 256, 256>>>(W, wq, nblk_w, 1);

    static bool attr_set = false;
    if (!attr_set) {
        cudaFuncSetAttribute(gemm_kernel,
                             cudaFuncAttributeMaxDynamicSharedMemorySize,
                             GEMM_SMEM);
        attr_set = true;
    }
    dim3 grid(N / BN, M / BM);
    gemm_kernel<<<grid, 512, GEMM_SMEM>>>(xq, wq, b, out, M, N, K);
}

// round 8
// speedup vs baseline: 1.5992x; 1.3418x over previous
#include <cuda_runtime.h>
#include <cuda_fp16.h>
#include <cuda_bf16.h>
#include <cstdint>

// ---------------------------------------------------------------------------
// QuantLinear: nvfp4 fake-quant(x), fake-quant(W), then x_q @ W_q^T + b
// x: [4,2048,4096] f32 -> M=8192,K=4096 ; W: [4096,4096] ; b:[4096] ; out f32
// R7: legacy-HMMA GEMM tuned: BK=64/3-stage cp.async, 1 sync/iter, ldmatrix,
//     exact fp16 operands (q*scq) with global scales folded into epilogue.
// ---------------------------------------------------------------------------

#define MAX_M 8192
#define KDIM  4096
#define NDIM  4096

__device__ unsigned int g_amax[2];
__device__ __half g_xq[(size_t)MAX_M * KDIM];   // 64 MB  (holds q*scq, exact)
__device__ __half g_wq[(size_t)NDIM * KDIM];    // 32 MB

// ---------------------------------------------------------------------------
// round-to-tiny-float, bit-exact vs reference chain (see R6 comment).
// ---------------------------------------------------------------------------
__device__ __forceinline__ float roundfp(float x, int mant, int min_exp, float maxv) {
    float a = fabsf(x);
    int e = (int)(__float_as_uint(a) >> 23) - 127;   // floor(log2 a) for normals
    if (e < min_exp) e = min_exp;
    float step  = __uint_as_float((unsigned)(e - mant + 127) << 23);
    float istep = __uint_as_float((unsigned)(127 - (e - mant)) << 23);
    float q = fminf(__fmul_rn(rintf(__fmul_rn(a, istep)), step), maxv);
    return (x < 0.0f) ? -q : q;
}

__global__ void init_kernel() { g_amax[0] = 0u; g_amax[1] = 0u; }

__global__ void amax_kernel(const float* __restrict__ x, int n4, int slot) {
    float m = 0.0f;
    for (int i = blockIdx.x * blockDim.x + threadIdx.x; i < n4;
         i += gridDim.x * blockDim.x) {
        float4 v = reinterpret_cast<const float4*>(x)[i];
        m = fmaxf(m, fmaxf(fmaxf(fabsf(v.x), fabsf(v.y)),
                           fmaxf(fabsf(v.z), fabsf(v.w))));
    }
    #pragma unroll
    for (int o = 16; o; o >>= 1)
        m = fmaxf(m, __shfl_xor_sync(0xffffffffu, m, o));
    if ((threadIdx.x & 31) == 0)
        atomicMax(&g_amax[slot], __float_as_uint(m));
}

// One thread = one 16-element nvfp4 micro-block. Output is q*scq:
// q (e2m1 grid, <=2 sig bits) times scq (e4m3 grid, <=4 sig bits) is EXACT
// in fp16 (<=6 sig bits, exponent range [-10, 12]). The global scales
// gsx*gsw are divided out in the GEMM epilogue.
__global__ void quant_kernel(const float* __restrict__ in,
                             __half* __restrict__ out,
                             int nblk, int slot) {
    int b = blockIdx.x * blockDim.x + threadIdx.x;
    if (b >= nblk) return;
    float amax   = __uint_as_float(g_amax[slot]);
    float gscale = __fdiv_rn(2688.0f, amax);   // 448 * 6 / amax

    const float4* p = reinterpret_cast<const float4*>(in + (size_t)b * 16);
    float4 v0 = p[0], v1 = p[1], v2 = p[2], v3 = p[3];
    float vals[16] = {v0.x, v0.y, v0.z, v0.w, v1.x, v1.y, v1.z, v1.w,
                      v2.x, v2.y, v2.z, v2.w, v3.x, v3.y, v3.z, v3.w};

    float bmax = 0.0f;
    #pragma unroll
    for (int i = 0; i < 16; i++) bmax = fmaxf(bmax, fabsf(vals[i]));

    float sv  = __fmul_rn(__fdiv_rn(bmax, 6.0f), gscale);
    float scq = roundfp(sv, 3, -6, 448.0f);
    float sc  = __fdiv_rn(scq, gscale);       // same rounding chain as ref
    float scs = (sc > 0.0f) ? sc : 1.0f;

    __half h[16];
    #pragma unroll
    for (int i = 0; i < 16; i++) {
        float q = roundfp(__fdiv_rn(vals[i], scs), 1, 0, 6.0f);
        h[i] = __float2half_rn(__fmul_rn(q, scq));   // exact in fp16
    }
    uint4* o = reinterpret_cast<uint4*>(out + (size_t)b * 16);
    o[0] = reinterpret_cast<uint4*>(h)[0];
    o[1] = reinterpret_cast<uint4*>(h)[1];
}

// ---------------------------------------------------------------------------
// HMMA GEMM: C = (A' * B'^T) / (gsx*gsw) + bias
// CTA 256(M) x 128(N), BK=64, 3-stage cp.async, 512 thr = 16 warps (4x4),
// warp tile 64x32, ldmatrix.x4 operand loads, one __syncthreads per K-iter.
// ---------------------------------------------------------------------------
#define BM 256
#define BN 128
#define BK 64
#define STAGES 3
#define BKP 72                                   // padded row (halves)
#define A_STG (BM * BKP)                         // 18432 halves
#define B_STG (BN * BKP)                         // 9216 halves
#define STG_HALVES (A_STG + B_STG)               // 27648 halves = 55296 B
#define STG_BYTES (STG_HALVES * 2)
#define GEMM_SMEM (STAGES * STG_BYTES + 512)     // 166400

__device__ __forceinline__ uint32_t smem_u32(const void* p) {
    uint32_t a;
    asm("{ .reg .u64 t; cvta.to.shared.u64 t, %1; cvt.u32.u64 %0, t; }"
        : "=r"(a) : "l"(p));
    return a;
}
__device__ __forceinline__ void cpa16(uint32_t s, const void* g) {
    asm volatile("cp.async.cg.shared.global [%0], [%1], 16;"
                 :: "r"(s), "l"(g) : "memory");
}
__device__ __forceinline__ void cpa_commit() {
    asm volatile("cp.async.commit_group;" ::: "memory");
}
template <int N_>
__device__ __forceinline__ void cpa_wait() {
    asm volatile("cp.async.wait_group %0;" :: "n"(N_) : "memory");
}
__device__ __forceinline__ void ldsm_x4(uint32_t* r, uint32_t addr) {
    asm volatile("ldmatrix.sync.aligned.m8n8.x4.shared.b16 {%0,%1,%2,%3}, [%4];"
                 : "=r"(r[0]), "=r"(r[1]), "=r"(r[2]), "=r"(r[3]) : "r"(addr));
}
__device__ __forceinline__ void mma_16816(float* d, const uint32_t* a,
                                          const uint32_t* b) {
    asm volatile(
        "mma.sync.aligned.m16n8k16.row.col.f32.f16.f16.f32 "
        "{%0,%1,%2,%3}, {%4,%5,%6,%7}, {%8,%9}, {%0,%1,%2,%3};\n"
        : "+f"(d[0]), "+f"(d[1]), "+f"(d[2]), "+f"(d[3])
        : "r"(a[0]), "r"(a[1]), "r"(a[2]), "r"(a[3]), "r"(b[0]), "r"(b[1]));
}

__global__ void __launch_bounds__(512, 1) gemm_kernel(
    const __half* __restrict__ A,   // [M,K] = q*scq (exact fp16)
    const __half* __restrict__ B,   // [N,K]
    const float* __restrict__ bias, // [N]
    float* __restrict__ C,          // [M,N]
    int M, int N, int K) {
    extern __shared__ char smem_raw[];
    __half* stg   = (__half*)smem_raw;
    float*  biass = (float*)(smem_raw + STAGES * STG_BYTES);

    const int t    = threadIdx.x;
    const int m0   = blockIdx.y * BM;
    const int n0   = blockIdx.x * BN;
    const int warp = t >> 5;
    const int lane = t & 31;
    const int wm   = (warp >> 2) * 64;   // 4 warp-rows
    const int wn   = (warp & 3) * 32;    // 4 warp-cols
    const int ar   = lane >> 2;
    const int ac   = (lane & 3) * 2;

    if (t < BN) biass[t] = bias[n0 + t];

    const uint32_t stg_s = smem_u32(stg);
    const int nK = K / BK;               // 64

    // cp.async slots: A = 2048 16B chunks (4/thread), B = 1024 (2/thread).
    // chunk c: row = c>>3 (8 chunks per 64-half row), col = (c&7)*8 halves.
    const __half* Abase = A + (size_t)m0 * K;
    const __half* Bbase = B + (size_t)n0 * K;

    auto load_stage = [&](int kt, int s) {
        const uint32_t ab = stg_s + (uint32_t)s * STG_BYTES;
        const uint32_t bb = ab + A_STG * 2;
        const __half* Ag = Abase + (size_t)kt * BK;
        const __half* Bg = Bbase + (size_t)kt * BK;
        #pragma unroll
        for (int i = 0; i < 4; i++) {
            int c = t + i * 512;
            int r = c >> 3, col = (c & 7) * 8;
            cpa16(ab + (r * BKP + col) * 2, Ag + (size_t)r * K + col);
        }
        #pragma unroll
        for (int i = 0; i < 2; i++) {
            int c = t + i * 512;
            int r = c >> 3, col = (c & 7) * 8;
            cpa16(bb + (r * BKP + col) * 2, Bg + (size_t)r * K + col);
        }
    };

    // ldmatrix per-warp static byte offsets (within a stage, at kk=0)
    // A tile i: rows wm+i*16+(lane&15), k-col (lane>>4)*8
    uint32_t a_off[4], b_off[2];
    {
        int arow = (lane & 15), akk = (lane >> 4) * 8;
        #pragma unroll
        for (int i = 0; i < 4; i++)
            a_off[i] = ((wm + i * 16 + arow) * BKP + akk) * 2;
        // B pair jj: rows wn+jj*16+(lane&7)+((lane>>4)<<3), k-col ((lane>>3)&1)*8
        int brow = (lane & 7) + ((lane >> 4) << 3), bkk = ((lane >> 3) & 1) * 8;
        #pragma unroll
        for (int jj = 0; jj < 2; jj++)
            b_off[jj] = (uint32_t)(A_STG * 2) +
                        ((wn + jj * 16 + brow) * BKP + bkk) * 2;
    }

    // prologue
    load_stage(0, 0); cpa_commit();
    load_stage(1, 1); cpa_commit();

    float acc[4][4][4];
    #pragma unroll
    for (int i = 0; i < 4; i++)
        #pragma unroll
        for (int j = 0; j < 4; j++)
            #pragma unroll
            for (int r = 0; r < 4; r++) acc[i][j][r] = 0.0f;

    int cs = 0;             // compute stage
    int ls = STAGES - 1;    // load stage (2)
    for (int k = 0; k < nK; k++) {
        cpa_wait<STAGES - 2>();
        __syncthreads();

        int kl = k + STAGES - 1;
        if (kl < nK) load_stage(kl, ls);
        cpa_commit();       // always commit (empty group in tail)
        if (++ls == STAGES) ls = 0;

        const uint32_t sbase = stg_s + (uint32_t)cs * STG_BYTES;
        if (++cs == STAGES) cs = 0;

        #pragma unroll
        for (int kk = 0; kk < BK; kk += 16) {
            uint32_t afr[4][4], bfr[4][2];
            #pragma unroll
            for (int i = 0; i < 4; i++)
                ldsm_x4(afr[i], sbase + a_off[i] + kk * 2);
            #pragma unroll
            for (int jj = 0; jj < 2; jj++) {
                uint32_t rr[4];
                ldsm_x4(rr, sbase + b_off[jj] + kk * 2);
                bfr[jj * 2][0] = rr[0]; bfr[jj * 2][1] = rr[1];
                bfr[jj * 2 + 1][0] = rr[2]; bfr[jj * 2 + 1][1] = rr[3];
            }
            #pragma unroll
            for (int i = 0; i < 4; i++)
                #pragma unroll
                for (int j = 0; j < 4; j++)
                    mma_16816(acc[i][j], afr[i], bfr[j]);
        }
    }

    // epilogue: undo global scales, + bias, fp32 out
    float ax = __uint_as_float(g_amax[0]);
    float aw = __uint_as_float(g_amax[1]);
    float gx = __fdiv_rn(2688.0f, ax);
    float gw = __fdiv_rn(2688.0f, aw);
    float inv = __fdiv_rn(1.0f, __fmul_rn(gx, gw));

    #pragma unroll
    for (int i = 0; i < 4; i++) {
        #pragma unroll
        for (int j = 0; j < 4; j++) {
            int r  = m0 + wm + i * 16 + ar;
            int nn = wn + j * 8 + ac;
            float bv0 = biass[nn], bv1 = biass[nn + 1];
            float2 o0 = {fmaf(acc[i][j][0], inv, bv0), fmaf(acc[i][j][1], inv, bv1)};
            float2 o1 = {fmaf(acc[i][j][2], inv, bv0), fmaf(acc[i][j][3], inv, bv1)};
            *(float2*)&C[(size_t)r * N + n0 + nn]       = o0;
            *(float2*)&C[(size_t)(r + 8) * N + n0 + nn] = o1;
        }
    }
}

// ---------------------------------------------------------------------------
extern "C" void kernel_launch(void* const* d_in, const int* in_sizes, int n_in,
                              void* d_out, int out_size) {
    const float* x = (const float*)d_in[0];
    const float* W = (const float*)d_in[1];
    const float* b = (const float*)d_in[2];
    float* out = (float*)d_out;

    const int K = KDIM;
    const int N = NDIM;
    const int M = in_sizes[0] / K;          // 8192

    __half* xq;  cudaGetSymbolAddress((void**)&xq, g_xq);
    __half* wq;  cudaGetSymbolAddress((void**)&wq, g_wq);

    init_kernel<<<1, 1>>>();
    amax_kernel<<<1024, 256>>>(x, (M * K) / 4, 0);
    amax_kernel<<<1024, 256>>>(W, (N * K) / 4, 1);

    int nblk_x = (M * K) / 16;
    int nblk_w = (N * K) / 16;
    quant_kernel<<<(nblk_x + 255) / 256, 256>>>(x, xq, nblk_x, 0);
    quant_kernel<<<(nblk_w + 255) / 256, 256>>>(W, wq, nblk_w, 1);

    static bool attr_set = false;
    if (!attr_set) {
        cudaFuncSetAttribute(gemm_kernel,
                             cudaFuncAttributeMaxDynamicSharedMemorySize,
                             GEMM_SMEM);
        attr_set = true;
    }
    dim3 grid(N / BN, M / BM);
    gemm_kernel<<<grid, 512, GEMM_SMEM>>>(xq, wq, b, out, M, N, K);
}